// round 1
// baseline (speedup 1.0000x reference)
#include <cuda_runtime.h>
#include <cstdint>

// Problem constants (from reference setup_inputs)
#define BB 4
#define NN 65536
#define MM 12
#define FF 2048
#define DD 64

// Tile of points per block
#define TP 128
#define PAD (TP + 1)   // 129, odd stride -> conflict-free channel-major smem writes
#define THREADS 256

template <bool BOUNDARY>
__global__ __launch_bounds__(THREADS)
void fuse_kernel(const float* __restrict__ data,     // [B, N, 12]
                 const float* __restrict__ feature,  // [B, F, D]
                 float* __restrict__ out)            // [B, C, N]
{
    constexpr int C = BOUNDARY ? (4 + DD) : (3 + DD);   // 68 or 67
    constexpr int BASE = BOUNDARY ? 4 : 3;

    __shared__ float s_out[C * PAD];
    __shared__ float s_data[TP * MM];

    const int tile = blockIdx.x;                 // 0 .. B*N/TP - 1
    const int tilesPerB = NN / TP;               // 512
    const int b = tile / tilesPerB;
    const int n0 = (tile - b * tilesPerB) * TP;

    const float* dbase = data + ((size_t)b * NN + n0) * MM;
    const int tid = threadIdx.x;

    // Stage point records (coalesced): 128 points x 12 floats = 1536 floats
    #pragma unroll
    for (int i = tid; i < TP * MM; i += THREADS) {
        s_data[i] = dbase[i];
    }
    __syncthreads();

    const int warp = tid >> 5;
    const int lane = tid & 31;
    const float* __restrict__ fb = feature + (size_t)b * FF * DD;

    // Each warp processes points warp, warp+8, ... (16 points)
    #pragma unroll 1
    for (int p = warp; p < TP; p += (THREADS / 32)) {
        const float* dr = s_data + p * MM;
        float acc0 = 0.0f;
        float acc1 = 0.0f;
        #pragma unroll
        for (int k = 0; k < 4; k++) {
            // idx: truncate-toward-zero then clamp (matches astype(int32)+clip)
            int idx = (int)dr[3 + k];
            idx = min(max(idx, 0), FF - 1);
            float w = dr[7 + k];
            float invw = 1.0f / fmaxf(w, 1e-10f);
            const float* row = fb + (size_t)idx * DD;
            // lane l covers channels l and l+32: two fully-coalesced 128B row reads
            acc0 = fmaf(__ldg(row + lane),      invw, acc0);
            acc1 = fmaf(__ldg(row + lane + 32), invw, acc1);
        }
        // Transposed staging: channel-major, stride PAD=129 (adjacent lanes ->
        // adjacent channels -> adjacent banks; conflict-free)
        s_out[(BASE + lane) * PAD + p]      = acc0;
        s_out[(BASE + lane + 32) * PAD + p] = acc1;
        if (lane < 3) s_out[lane * PAD + p] = dr[lane];
        if (BOUNDARY && lane == 3) s_out[3 * PAD + p] = dr[MM - 1];
    }
    __syncthreads();

    // Coalesced write-out: each 128-thread group writes one channel row
    // (128 contiguous floats = 512B) of out[b, r, n0:n0+128]
    float* ob = out + (size_t)b * C * NN + n0;
    const int col = tid & (TP - 1);
    const int rOff = tid >> 7;   // 0 or 1
    #pragma unroll 1
    for (int r0 = 0; r0 < C; r0 += 2) {
        int r = r0 + rOff;
        if (r < C) {
            ob[(size_t)r * NN + col] = s_out[r * PAD + col];
        }
    }
}

extern "C" void kernel_launch(void* const* d_in, const int* in_sizes, int n_in,
                              void* d_out, int out_size)
{
    const float* pv_o   = (const float*)d_in[0];   // [4, 65536, 12]
    const float* pv_b   = (const float*)d_in[1];   // [4, 65536, 12]
    const float* feat_o = (const float*)d_in[2];   // [4, 2048, 64]
    const float* feat_b = (const float*)d_in[3];   // [4, 2048, 64]

    float* out_o = (float*)d_out;                               // [4, 67, 65536]
    float* out_b = out_o + (size_t)BB * (3 + DD) * NN;          // [4, 68, 65536]

    dim3 grid(BB * NN / TP);   // 2048 blocks
    fuse_kernel<false><<<grid, THREADS>>>(pv_o, feat_o, out_o);
    fuse_kernel<true ><<<grid, THREADS>>>(pv_b, feat_b, out_b);
}

// round 3
// speedup vs baseline: 1.2557x; 1.2557x over previous
#include <cuda_runtime.h>
#include <cstdint>

// Problem constants (from reference setup_inputs)
#define BB 4
#define NN 65536
#define MM 12
#define FF 2048
#define DD 64

#define TP 128            // points per block tile
#define PAD (TP + 1)      // 129: odd stride -> conflict-free channel-major smem
#define THREADS 512
#define CMAX 68           // 4 + D (boundary case)

__global__ __launch_bounds__(THREADS)
void fuse_kernel(const float* __restrict__ data_o,   // [B, N, 12]
                 const float* __restrict__ data_b,   // [B, N, 12]
                 const float* __restrict__ feat_o,   // [B, F, D]
                 const float* __restrict__ feat_b,   // [B, F, D]
                 float* __restrict__ out_o,          // [B, 67, N]
                 float* __restrict__ out_b)          // [B, 68, N]
{
    __shared__ float s_out[CMAX * PAD];    // ~35 KB
    __shared__ float s_data[TP * MM];      //  6 KB

    const bool boundary = (blockIdx.y != 0);
    const int  C    = boundary ? 68 : 67;
    const int  BASE = boundary ? 4 : 3;

    const float* __restrict__ data    = boundary ? data_b : data_o;
    const float* __restrict__ feature = boundary ? feat_b : feat_o;
    float*       __restrict__ out     = boundary ? out_b  : out_o;

    const int tile = blockIdx.x;              // 0 .. B*N/TP - 1  (2048)
    const int tilesPerB = NN / TP;            // 512
    const int b  = tile / tilesPerB;
    const int n0 = (tile - b * tilesPerB) * TP;

    const float* dbase = data + ((size_t)b * NN + n0) * MM;
    const int tid = threadIdx.x;

    // Stage point records (coalesced): 128 points x 12 floats
    #pragma unroll
    for (int i = tid; i < TP * MM; i += THREADS) {
        s_data[i] = dbase[i];
    }
    __syncthreads();

    const int warp = tid >> 5;                // 0..15
    const int lane = tid & 31;
    const float* __restrict__ fb = feature + (size_t)b * FF * DD;

    // Each warp processes 8 points: warp, warp+16, ...
    #pragma unroll 1
    for (int p = warp; p < TP; p += (THREADS / 32)) {
        const float* dr = s_data + p * MM;
        float acc0 = 0.0f;
        float acc1 = 0.0f;
        #pragma unroll
        for (int k = 0; k < 4; k++) {
            // truncate-toward-zero then clamp (matches astype(int32)+clip)
            int idx = (int)dr[3 + k];
            idx = min(max(idx, 0), FF - 1);
            float invw = 1.0f / fmaxf(dr[7 + k], 1e-10f);
            const float* row = fb + (size_t)idx * DD;
            // lane l covers channels l and l+32: two coalesced 128B row reads
            acc0 = fmaf(__ldg(row + lane),      invw, acc0);
            acc1 = fmaf(__ldg(row + lane + 32), invw, acc1);
        }
        // Channel-major staging, stride 129 -> conflict-free
        s_out[(BASE + lane) * PAD + p]      = acc0;
        s_out[(BASE + lane + 32) * PAD + p] = acc1;
        if (lane < 3) s_out[lane * PAD + p] = dr[lane];
        if (boundary && lane == 3) s_out[3 * PAD + p] = dr[MM - 1];
    }
    __syncthreads();

    // Coalesced write-out: each 128-thread group writes one channel row
    // (128 contiguous floats = 512B) of out[b, r, n0:n0+128]
    float* ob = out + (size_t)b * C * NN + n0;
    const int col  = tid & (TP - 1);
    const int rOff = tid >> 7;               // 0..3
    #pragma unroll 1
    for (int r0 = 0; r0 < CMAX; r0 += 4) {
        int r = r0 + rOff;
        if (r < C) {
            ob[(size_t)r * NN + col] = s_out[r * PAD + col];
        }
    }
}

extern "C" void kernel_launch(void* const* d_in, const int* in_sizes, int n_in,
                              void* d_out, int out_size)
{
    const float* pv_o   = (const float*)d_in[0];   // [4, 65536, 12]
    const float* pv_b   = (const float*)d_in[1];   // [4, 65536, 12]
    const float* feat_o = (const float*)d_in[2];   // [4, 2048, 64]
    const float* feat_b = (const float*)d_in[3];   // [4, 2048, 64]

    float* out_o = (float*)d_out;                              // [4, 67, 65536]
    float* out_b = out_o + (size_t)BB * (3 + DD) * NN;         // [4, 68, 65536]

    dim3 grid(BB * NN / TP, 2);   // 2048 tiles x {plain, boundary}
    fuse_kernel<<<grid, THREADS>>>(pv_o, pv_b, feat_o, feat_b, out_o, out_b);
}

// round 4
// speedup vs baseline: 1.9585x; 1.5596x over previous
#include <cuda_runtime.h>
#include <cstdint>

// Problem constants (from reference setup_inputs)
#define BB 4
#define NN 65536
#define MM 12
#define FF 2048
#define DD 64

#define TP 128            // points per block tile
#define PAD (TP + 1)      // 129: odd stride -> conflict-free channel-major smem
#define THREADS 512
#define CMAX 68           // 4 + D (boundary case)

__global__ __launch_bounds__(THREADS)
void fuse_kernel(const float* __restrict__ data_o,   // [B, N, 12]
                 const float* __restrict__ data_b,   // [B, N, 12]
                 const float* __restrict__ feat_o,   // [B, F, D]
                 const float* __restrict__ feat_b,   // [B, F, D]
                 float* __restrict__ out_o,          // [B, 67, N]
                 float* __restrict__ out_b)          // [B, 68, N]
{
    __shared__ float s_out[CMAX * PAD];    // 35.1 KB
    __shared__ float s_data[TP * MM];      //  6.0 KB raw 12-float records
    __shared__ int4  s_off[TP];            //  2.0 KB byte offsets of 4 gather rows
    __shared__ float4 s_w[TP];             //  2.0 KB inverse weights

    const bool boundary = (blockIdx.y != 0);
    const int  BASE = boundary ? 4 : 3;
    const int  C    = boundary ? 68 : 67;

    const float* __restrict__ data    = boundary ? data_b : data_o;
    const float* __restrict__ feature = boundary ? feat_b : feat_o;
    float*       __restrict__ out     = boundary ? out_b  : out_o;

    const int tile = blockIdx.x;              // 0 .. B*N/TP - 1  (2048)
    const int tilesPerB = NN / TP;            // 512
    const int b  = tile / tilesPerB;
    const int n0 = (tile - b * tilesPerB) * TP;

    const int tid = threadIdx.x;

    // ---- Stage point records (fully coalesced) ----
    const float* dbase = data + ((size_t)b * NN + n0) * MM;
    #pragma unroll
    for (int i = tid; i < TP * MM; i += THREADS) {
        s_data[i] = dbase[i];
    }
    __syncthreads();

    // ---- Precompute per-point gather byte-offsets + inverse weights (once) ----
    if (tid < TP) {
        const float* dr = s_data + tid * MM;
        int4 off;
        // truncate-toward-zero then clamp (matches astype(int32)+clip); *256 bytes/row
        off.x = min(max((int)dr[3], 0), FF - 1) * (DD * 4);
        off.y = min(max((int)dr[4], 0), FF - 1) * (DD * 4);
        off.z = min(max((int)dr[5], 0), FF - 1) * (DD * 4);
        off.w = min(max((int)dr[6], 0), FF - 1) * (DD * 4);
        float4 iw;
        iw.x = 1.0f / fmaxf(dr[7],  1e-10f);
        iw.y = 1.0f / fmaxf(dr[8],  1e-10f);
        iw.z = 1.0f / fmaxf(dr[9],  1e-10f);
        iw.w = 1.0f / fmaxf(dr[10], 1e-10f);
        s_off[tid] = off;
        s_w[tid]   = iw;
        // passthrough channels
        s_out[0 * PAD + tid] = dr[0];
        s_out[1 * PAD + tid] = dr[1];
        s_out[2 * PAD + tid] = dr[2];
        if (boundary) s_out[3 * PAD + tid] = dr[11];
    }
    __syncthreads();

    // ---- Main gather: half-warp per point, float4 lanes ----
    const int warp = tid >> 5;                // 0..15
    const int lane = tid & 31;
    const int hw   = lane >> 4;               // 0/1: which point of the pair
    const int hl   = lane & 15;               // float4 slot within row (16*16B=256B)

    const char* __restrict__ fbB =
        (const char*)(feature + (size_t)b * FF * DD) + hl * 16;

    const int c0 = BASE + 4 * hl;             // first of 4 consecutive channels

    #pragma unroll 2
    for (int i = 0; i < 8; i += 2) {          // warp owns points [8*warp, 8*warp+8)
        const int p = warp * 8 + i + hw;
        const int4  off = s_off[p];
        const float4 w  = s_w[p];

        const float4 r0 = *(const float4*)(fbB + off.x);
        const float4 r1 = *(const float4*)(fbB + off.y);
        const float4 r2 = *(const float4*)(fbB + off.z);
        const float4 r3 = *(const float4*)(fbB + off.w);

        float4 acc;
        acc.x = fmaf(r0.x, w.x, fmaf(r1.x, w.y, fmaf(r2.x, w.z, r3.x * w.w)));
        acc.y = fmaf(r0.y, w.x, fmaf(r1.y, w.y, fmaf(r2.y, w.z, r3.y * w.w)));
        acc.z = fmaf(r0.z, w.x, fmaf(r1.z, w.y, fmaf(r2.z, w.z, r3.z * w.w)));
        acc.w = fmaf(r0.w, w.x, fmaf(r1.w, w.y, fmaf(r2.w, w.z, r3.w * w.w)));

        // channel-major staging, stride 129 (the two half-warps hit disjoint banks)
        s_out[(c0 + 0) * PAD + p] = acc.x;
        s_out[(c0 + 1) * PAD + p] = acc.y;
        s_out[(c0 + 2) * PAD + p] = acc.z;
        s_out[(c0 + 3) * PAD + p] = acc.w;
    }
    __syncthreads();

    // ---- Coalesced write-out: 4 channel rows per pass, 512B contiguous each ----
    float* ob = out + (size_t)b * C * NN + n0;
    const int col  = tid & (TP - 1);
    const int rOff = tid >> 7;               // 0..3
    #pragma unroll 1
    for (int r0w = 0; r0w < CMAX; r0w += 4) {
        const int r = r0w + rOff;
        if (r < C) {
            ob[(size_t)r * NN + col] = s_out[r * PAD + col];
        }
    }
}

extern "C" void kernel_launch(void* const* d_in, const int* in_sizes, int n_in,
                              void* d_out, int out_size)
{
    const float* pv_o   = (const float*)d_in[0];   // [4, 65536, 12]
    const float* pv_b   = (const float*)d_in[1];   // [4, 65536, 12]
    const float* feat_o = (const float*)d_in[2];   // [4, 2048, 64]
    const float* feat_b = (const float*)d_in[3];   // [4, 2048, 64]

    float* out_o = (float*)d_out;                              // [4, 67, 65536]
    float* out_b = out_o + (size_t)BB * (3 + DD) * NN;         // [4, 68, 65536]

    dim3 grid(BB * NN / TP, 2);   // 2048 tiles x {plain, boundary}
    fuse_kernel<<<grid, THREADS>>>(pv_o, pv_b, feat_o, feat_b, out_o, out_b);
}

// round 5
// speedup vs baseline: 2.1890x; 1.1177x over previous
#include <cuda_runtime.h>
#include <cstdint>

// Problem constants (from reference setup_inputs)
#define BB 4
#define NN 65536
#define MM 12
#define FF 2048
#define DD 64

#define TP 128            // points per block tile
#define SROW 128          // smem row stride (floats); conflicts handled by XOR swizzle
#define THREADS 512
#define CMAX 68           // 4 + D (boundary case)

__global__ __launch_bounds__(THREADS)
void fuse_kernel(const float* __restrict__ data_o,   // [B, N, 12]
                 const float* __restrict__ data_b,   // [B, N, 12]
                 const float* __restrict__ feat_o,   // [B, F, D]
                 const float* __restrict__ feat_b,   // [B, F, D]
                 float* __restrict__ out_o,          // [B, 67, N]
                 float* __restrict__ out_b)          // [B, 68, N]
{
    __shared__ float  s_out[CMAX * SROW];   // 34.0 KB
    __shared__ int4   s_off[TP];            //  2.0 KB byte offsets of 4 gather rows
    __shared__ float4 s_w[TP];              //  2.0 KB inverse weights

    const bool boundary = (blockIdx.y != 0);
    const int  BASE = boundary ? 4 : 3;
    const int  C    = boundary ? 68 : 67;

    const float* __restrict__ data    = boundary ? data_b : data_o;
    const float* __restrict__ feature = boundary ? feat_b : feat_o;
    float*       __restrict__ out     = boundary ? out_b  : out_o;

    const int tile = blockIdx.x;              // 0 .. B*N/TP - 1  (2048)
    const int tilesPerB = NN / TP;            // 512
    const int b  = tile / tilesPerB;
    const int n0 = (tile - b * tilesPerB) * TP;

    const int tid = threadIdx.x;

    // ---- Precompute: thread t owns point t; 3 direct LDG.128 of its record ----
    if (tid < TP) {
        const float* dr = data + ((size_t)b * NN + n0 + tid) * MM;
        const float4 v0 = *(const float4*)(dr + 0);   // x, y, z, idx0
        const float4 v1 = *(const float4*)(dr + 4);   // idx1, idx2, idx3, w0
        const float4 v2 = *(const float4*)(dr + 8);   // w1, w2, w3, bnd

        int4 off;     // byte offsets (truncate-toward-zero then clamp; *256 B/row)
        off.x = min(max((int)v0.w, 0), FF - 1) * (DD * 4);
        off.y = min(max((int)v1.x, 0), FF - 1) * (DD * 4);
        off.z = min(max((int)v1.y, 0), FF - 1) * (DD * 4);
        off.w = min(max((int)v1.z, 0), FF - 1) * (DD * 4);
        float4 iw;
        iw.x = 1.0f / fmaxf(v1.w, 1e-10f);
        iw.y = 1.0f / fmaxf(v2.x, 1e-10f);
        iw.z = 1.0f / fmaxf(v2.y, 1e-10f);
        iw.w = 1.0f / fmaxf(v2.z, 1e-10f);
        s_off[tid] = off;
        s_w[tid]   = iw;

        // passthrough channels (unswizzled rows)
        s_out[0 * SROW + tid] = v0.x;
        s_out[1 * SROW + tid] = v0.y;
        s_out[2 * SROW + tid] = v0.z;
        if (boundary) s_out[3 * SROW + tid] = v2.w;
    }
    __syncthreads();

    // ---- Main gather: half-warp per point, float4 lanes ----
    const int warp = tid >> 5;                // 0..15
    const int lane = tid & 31;
    const int hw   = lane >> 4;               // 0/1: which point of the pair
    const int hl   = lane & 15;               // float4 slot within row (16*16B=256B)

    const char* __restrict__ fbB =
        (const char*)(feature + (size_t)b * FF * DD) + hl * 16;

    const int c0  = BASE + 4 * hl;            // first of 4 consecutive channels
    // XOR swizzle: breaks all STS bank conflicts (proof in commit message)
    const int swz = ((hl & 7) << 2) | ((hl >= 8) ? 2 : 0);

    #pragma unroll 2
    for (int i = 0; i < 8; i += 2) {          // warp owns points [8*warp, 8*warp+8)
        const int p = warp * 8 + i + hw;
        const int4   off = s_off[p];          // broadcast LDS
        const float4 w   = s_w[p];

        const float4 r0 = *(const float4*)(fbB + off.x);
        const float4 r1 = *(const float4*)(fbB + off.y);
        const float4 r2 = *(const float4*)(fbB + off.z);
        const float4 r3 = *(const float4*)(fbB + off.w);

        float4 acc;
        acc.x = fmaf(r0.x, w.x, fmaf(r1.x, w.y, fmaf(r2.x, w.z, r3.x * w.w)));
        acc.y = fmaf(r0.y, w.x, fmaf(r1.y, w.y, fmaf(r2.y, w.z, r3.y * w.w)));
        acc.z = fmaf(r0.z, w.x, fmaf(r1.z, w.y, fmaf(r2.z, w.z, r3.z * w.w)));
        acc.w = fmaf(r0.w, w.x, fmaf(r1.w, w.y, fmaf(r2.w, w.z, r3.w * w.w)));

        const int ps = p ^ swz;               // swizzled slot for point p
        s_out[(c0 + 0) * SROW + ps] = acc.x;
        s_out[(c0 + 1) * SROW + ps] = acc.y;
        s_out[(c0 + 2) * SROW + ps] = acc.z;
        s_out[(c0 + 3) * SROW + ps] = acc.w;
    }
    __syncthreads();

    // ---- Vectorized write-out: warp per channel row, LDS.128 + STG.128 ----
    // Slot group 4*lane of row r holds points 4*(lane ^ f4) (+ half-swap if upper)
    float* ob = out + (size_t)b * C * NN + n0;
    #pragma unroll
    for (int it = 0; it < 5; it++) {          // ceil(68/16) passes
        const int r = it * 16 + warp;
        if (r < C) {
            const int rf = r - BASE;
            float4 v = *(const float4*)&s_out[r * SROW + 4 * lane];
            int g = lane;
            if (rf >= 0) {
                g = lane ^ ((rf >> 2) & 7);
                if (rf >= 32) {               // upper channels: components ^2
                    v = make_float4(v.z, v.w, v.x, v.y);
                }
            }
            *(float4*)(ob + (size_t)r * NN + 4 * g) = v;
        }
    }
}

extern "C" void kernel_launch(void* const* d_in, const int* in_sizes, int n_in,
                              void* d_out, int out_size)
{
    const float* pv_o   = (const float*)d_in[0];   // [4, 65536, 12]
    const float* pv_b   = (const float*)d_in[1];   // [4, 65536, 12]
    const float* feat_o = (const float*)d_in[2];   // [4, 2048, 64]
    const float* feat_b = (const float*)d_in[3];   // [4, 2048, 64]

    float* out_o = (float*)d_out;                              // [4, 67, 65536]
    float* out_b = out_o + (size_t)BB * (3 + DD) * NN;         // [4, 68, 65536]

    dim3 grid(BB * NN / TP, 2);   // 2048 tiles x {plain, boundary}
    fuse_kernel<<<grid, THREADS>>>(pv_o, pv_b, feat_o, feat_b, out_o, out_b);
}